// round 16
// baseline (speedup 1.0000x reference)
#include <cuda_runtime.h>
#include <cstdint>

#define NB    8
#define CDIM  64
#define HH    256
#define WW    256
#define EPSV  1e-5f
#define CPP   8                  // partial-sum CTAs per plane
#define W4    (WW / 4)

// scratch (allocation-free rule: device globals)
__device__ float g_part[NB * CDIM * CPP];   // per-CTA partial plane sums

// ---- 256-bit global memory ops (sm_10x) ----
__device__ __forceinline__ void ldg256(const float* p, float* d) {
    uint32_t r0, r1, r2, r3, r4, r5, r6, r7;
    asm volatile("ld.global.nc.v8.b32 {%0,%1,%2,%3,%4,%5,%6,%7}, [%8];"
                 : "=r"(r0), "=r"(r1), "=r"(r2), "=r"(r3),
                   "=r"(r4), "=r"(r5), "=r"(r6), "=r"(r7) : "l"(p));
    d[0] = __uint_as_float(r0); d[1] = __uint_as_float(r1);
    d[2] = __uint_as_float(r2); d[3] = __uint_as_float(r3);
    d[4] = __uint_as_float(r4); d[5] = __uint_as_float(r5);
    d[6] = __uint_as_float(r6); d[7] = __uint_as_float(r7);
}
__device__ __forceinline__ void stg256_cs(float* p, const float* s) {
    asm volatile("st.global.cs.v8.b32 [%0], {%1,%2,%3,%4,%5,%6,%7,%8};"
                 :: "l"(p),
                    "r"(__float_as_uint(s[0])), "r"(__float_as_uint(s[1])),
                    "r"(__float_as_uint(s[2])), "r"(__float_as_uint(s[3])),
                    "r"(__float_as_uint(s[4])), "r"(__float_as_uint(s[5])),
                    "r"(__float_as_uint(s[6])), "r"(__float_as_uint(s[7]))
                 : "memory");
}

// ---------------- Kernel 1: fine-grained partial plane sums ----------------
__global__ void __launch_bounds__(256) part_kernel(const float* __restrict__ x) {
    int bid   = blockIdx.x;                  // 0..4095
    int plane = bid >> 3;
    int seg   = bid & (CPP - 1);
    const float4* p = (const float4*)(x + (size_t)plane * HH * WW) + seg * (HH / CPP) * W4;
    float s = 0.f;
    #pragma unroll
    for (int j = 0; j < (HH / CPP) * W4 / 256; j++) {
        float4 v = p[threadIdx.x + j * 256];
        s += (v.x + v.y) + (v.z + v.w);
    }
    #pragma unroll
    for (int o = 16; o > 0; o >>= 1)
        s += __shfl_down_sync(0xFFFFFFFFu, s, o);
    __shared__ float red[8];
    if ((threadIdx.x & 31) == 0) red[threadIdx.x >> 5] = s;
    __syncthreads();
    if (threadIdx.x == 0) {
        float t = red[0];
        #pragma unroll
        for (int w = 1; w < 8; w++) t += red[w];
        g_part[bid] = t;
    }
}

// ---------------- Kernel 2: fused gap-reduce + taps + strip conv (256-bit) ----------------
// grid = 2048 blocks (4 per plane), 256 threads, reverse plane order.
// thread: g = t&31 (8-float column group), chunk = t>>5 -> 8 rows each.
__global__ void __launch_bounds__(256) conv_kernel(
        const float* __restrict__ x, float* __restrict__ out,
        const float* __restrict__ wH, const float* __restrict__ gH,
        const float* __restrict__ bH, const float* __restrict__ mH,
        const float* __restrict__ vH,
        const float* __restrict__ wW, const float* __restrict__ gW,
        const float* __restrict__ bW, const float* __restrict__ mW,
        const float* __restrict__ vW) {
    int plane = (NB * CDIM - 1) - (blockIdx.x >> 2);   // 511..0 (reverse)
    int quart = blockIdx.x & 3;
    int n   = plane >> 6;
    int cch = plane & 63;
    int t = threadIdx.x;
    int g = t & 31;                          // 8-float group 0..31
    int h0 = quart * 64 + (t >> 5) * 8;      // 8 rows per thread

    __shared__ float sgap[CDIM];
    __shared__ float taps[6];

    // gap vector: fixed-order 8-way reduction of partials (deterministic, L2-hot)
    if (t < CDIM) {
        const float* pp = &g_part[(n * CDIM + t) * CPP];
        float a = 0.f;
        #pragma unroll
        for (int q = 0; q < CPP; q++) a += pp[q];
        sgap[t] = a * (1.0f / (HH * WW));
    }
    __syncthreads();

    if (t < 6) {
        int branch = t / 3;
        int k = t - branch * 3;
        int row = cch * 3 + k;
        const float* w  = branch ? wW : wH;
        const float* gg = branch ? gW : gH;
        const float* bb = branch ? bW : bH;
        const float* mm = branch ? mW : mH;
        const float* vv = branch ? vW : vH;
        const float* wr = w + row * CDIM;
        float s = 0.f;
        #pragma unroll
        for (int c = 0; c < CDIM; c++) s += sgap[c] * wr[c];
        float f = (s - mm[row]) * (gg[row] * rsqrtf(vv[row] + EPSV)) + bb[row];
        taps[t] = tanhf(f);
    }
    __syncthreads();

    float fh0 = taps[0], fh1 = taps[1], fh2 = taps[2];
    float fw0 = taps[3], fw1 = taps[4], fw2 = taps[5];

    const float* xp = x + (size_t)plane * HH * WW;
    float* o1 = out + ((size_t)n * 2 * CDIM + cch) * HH * WW;
    float* o2 = o1 + (size_t)CDIM * HH * WW;
    int col0 = 8 * g;

    auto process = [&](int h, const float* up, const float* ce, const float* dn) {
        float xl = (g == 0)  ? ce[1] : xp[h * WW + col0 - 1];   // reflect left
        float xr = (g == 31) ? ce[6] : xp[h * WW + col0 + 8];   // reflect right
        float ho[8], vo[8];
        ho[0] = fh0 * xl + fh1 * ce[0] + fh2 * ce[1];
        #pragma unroll
        for (int j = 1; j < 7; j++)
            ho[j] = fh0 * ce[j - 1] + fh1 * ce[j] + fh2 * ce[j + 1];
        ho[7] = fh0 * ce[6] + fh1 * ce[7] + fh2 * xr;
        #pragma unroll
        for (int j = 0; j < 8; j++)
            vo[j] = fw0 * up[j] + fw1 * ce[j] + fw2 * dn[j];
        stg256_cs(o1 + h * WW + col0, ho);
        stg256_cs(o2 + h * WW + col0, vo);
    };

    float u[8], c[8], d0[8], d1[8];
    int hu = (h0 == 0) ? 1 : h0 - 1;         // reflect top
    ldg256(xp + hu * WW + col0, u);
    ldg256(xp + h0 * WW + col0, c);

    #pragma unroll
    for (int hb = 0; hb < 8; hb += 2) {
        int h = h0 + hb;
        int r1 = h + 1;
        int r2 = (h + 2 > HH - 1) ? HH - 2 : h + 2;   // reflect bottom
        ldg256(xp + r1 * WW + col0, d0);
        ldg256(xp + r2 * WW + col0, d1);
        process(h,     u, c,  d0);
        process(h + 1, c, d0, d1);
        #pragma unroll
        for (int j = 0; j < 8; j++) { u[j] = d0[j]; c[j] = d1[j]; }
    }
}

extern "C" void kernel_launch(void* const* d_in, const int* in_sizes, int n_in,
                              void* d_out, int out_size) {
    const float* x  = (const float*)d_in[0];
    const float* wH = (const float*)d_in[1];
    const float* gH = (const float*)d_in[2];
    const float* bH = (const float*)d_in[3];
    const float* mH = (const float*)d_in[4];
    const float* vH = (const float*)d_in[5];
    const float* wW = (const float*)d_in[6];
    const float* gW = (const float*)d_in[7];
    const float* bW = (const float*)d_in[8];
    const float* mW = (const float*)d_in[9];
    const float* vW = (const float*)d_in[10];
    float* out = (float*)d_out;

    part_kernel<<<NB * CDIM * CPP, 256>>>(x);
    conv_kernel<<<4 * NB * CDIM, 256>>>(x, out, wH, gH, bH, mH, vH,
                                        wW, gW, bW, mW, vW);
}